// round 8
// baseline (speedup 1.0000x reference)
#include <cuda_runtime.h>

typedef unsigned long long ull;

#define C_ 64
#define D_ 32
#define S_ 32
#define HW_ 4096
#define DHW_ 131072

#define RX 258                    /* x-tile row stride: [d][c*4+w], 4 pixels */
#define OFF_XT 0
#define N_R1 8448                 /* max(x-tile 32*258=8256, otile 2*64*66=8448) */
#define OT_ROWF 66
#define OTW 4224                  /* per-warp otile stride */
#define OFF_SC N_R1
#define SC_ROWF 68                /* kT/vS row stride (shared buffer) */
#define SCW 2176                  /* per-warp scratch (32 rows x 68) */
#define SMEM_FLOATS (OFF_SC + 2*SCW)   /* 12800 floats = 51200 B */

__constant__ float cWKT[C_*S_];   /* [c][s] transposed */
__constant__ float cWQT[C_*S_];
__constant__ float cWVT[C_*S_];
__constant__ float cWO[C_*S_];    /* [c][s] native */
__constant__ float cBK[S_];
__constant__ float cBQ[S_];
__constant__ float cBV[S_];
__constant__ float cBO[C_];

__device__ float g_wt[3*C_*S_];   /* transpose staging */

__global__ void transpose_weights(const float* __restrict__ Wk,
                                  const float* __restrict__ Wq,
                                  const float* __restrict__ Wv)
{
    const int i = blockIdx.x * blockDim.x + threadIdx.x;   /* i = s*64 + c */
    if (i < S_*C_) {
        const int c = i & 63;
        const int s = i >> 6;
        g_wt[             c*S_ + s] = Wk[i];
        g_wt[  S_*C_ +    c*S_ + s] = Wq[i];
        g_wt[2*S_*C_ +    c*S_ + s] = Wv[i];
    }
}

__device__ __forceinline__ ull f2fma(ull a, ull b, ull c) {
    ull d; asm("fma.rn.f32x2 %0,%1,%2,%3;" : "=l"(d) : "l"(a), "l"(b), "l"(c)); return d;
}
__device__ __forceinline__ ull f2add(ull a, ull b) {
    ull d; asm("add.rn.f32x2 %0,%1,%2;" : "=l"(d) : "l"(a), "l"(b)); return d;
}
__device__ __forceinline__ ull f2mul(ull a, ull b) {
    ull d; asm("mul.rn.f32x2 %0,%1,%2;" : "=l"(d) : "l"(a), "l"(b)); return d;
}
__device__ __forceinline__ ull f2dup(float x) {
    ull d; asm("mov.b64 %0,{%1,%1};" : "=l"(d) : "f"(x)); return d;
}
__device__ __forceinline__ ull f2pack(float x, float y) {
    ull d; asm("mov.b64 %0,{%1,%2};" : "=l"(d) : "f"(x), "f"(y)); return d;
}
__device__ __forceinline__ float2 f2unpack(ull a) {
    float lo, hi; asm("mov.b64 {%0,%1},%2;" : "=f"(lo), "=f"(hi) : "l"(a));
    return make_float2(lo, hi);
}

/* projection pass: 2 pixels, s-pair accums per pixel; weights from constant [c][s] */
#define PROJ_PASS(CWT, accA, accB) {                                         \
    _Pragma("unroll 4")                                                      \
    for (int c = 0; c < C_; c++) {                                           \
        const ull xp = *(const ull*)&sm[OFF_XT + c*4 + xoff];                \
        const float2 xx = f2unpack(xp);                                      \
        const ull xad = f2dup(xx.x);                                         \
        const ull xbd = f2dup(xx.y);                                         \
        _Pragma("unroll")                                                    \
        for (int g = 0; g < 8; g++) {                                        \
            const ulonglong2 w2 = *(const ulonglong2*)&CWT[c*S_ + 4*g];      \
            accA[2*g]   = f2fma(w2.x, xad, accA[2*g]);                       \
            accA[2*g+1] = f2fma(w2.y, xad, accA[2*g+1]);                     \
            accB[2*g]   = f2fma(w2.x, xbd, accB[2*g]);                       \
            accB[2*g+1] = f2fma(w2.y, xbd, accB[2*g+1]);                     \
        }                                                                    \
    }                                                                        \
}

__global__ void __launch_bounds__(64, 4)
attn_fused_kernel(const float* __restrict__ x, float* __restrict__ out)
{
    extern __shared__ float sm[];
    const int tid = threadIdx.x;
    const int bx  = blockIdx.x;
    const int wt  = bx & 15;
    const int h   = (bx >> 4) & 63;
    const int b   = bx >> 10;
    const int w0  = wt * 4;
    const int xbase = b*C_*DHW_ + h*64 + w0;

    /* ---- stage x tile [d][c*4+w] ---- */
    for (int e = tid; e < C_*D_; e += 64) {
        const int d = e & 31;
        const int c = e >> 5;
        const float4 v4 = *(const float4*)&x[xbase + c*DHW_ + d*HW_];
        *(ull*)&sm[OFF_XT + d*RX + c*4]     = *(const ull*)&v4.x;
        *(ull*)&sm[OFF_XT + d*RX + c*4 + 2] = *(const ull*)&v4.z;
    }
    __syncthreads();

    const int warp = tid >> 5;           /* pixel pair (2*warp, 2*warp+1) */
    const int lane = tid & 31;           /* d (and j) */
    const int xoff = lane*RX + 2*warp;
    float* sc = sm + OFF_SC + warp*SCW;  /* shared kT-then-vS buffer */

    /* ================= K pass -> kT[i=lane][s] pixel-packed ================= */
    {
        ull kA[16], kB[16];
#pragma unroll
        for (int sp = 0; sp < 16; sp++) {
            const ull bb = *(const ull*)&cBK[2*sp];
            kA[sp] = bb; kB[sp] = bb;
        }
        PROJ_PASS(cWKT, kA, kB);
#pragma unroll
        for (int sp = 0; sp < 16; sp++) {
            const float2 a2 = f2unpack(kA[sp]);
            const float2 b2 = f2unpack(kB[sp]);
            ulonglong2 pr;
            pr.x = f2pack(a2.x, b2.x);
            pr.y = f2pack(a2.y, b2.y);
            *(ulonglong2*)&sc[lane*SC_ROWF + 4*sp] = pr;
        }
    }

    /* ================= Q pass (regs, pixel-packed per s) ================= */
    ull q2[32];
    {
        ull qA[16], qB[16];
#pragma unroll
        for (int sp = 0; sp < 16; sp++) {
            const ull bb = *(const ull*)&cBQ[2*sp];
            qA[sp] = bb; qB[sp] = bb;
        }
        PROJ_PASS(cWQT, qA, qB);
#pragma unroll
        for (int sp = 0; sp < 16; sp++) {
            const float2 a2 = f2unpack(qA[sp]);
            const float2 b2 = f2unpack(qB[sp]);
            q2[2*sp]   = f2pack(a2.x, b2.x);
            q2[2*sp+1] = f2pack(a2.y, b2.y);
        }
    }
    __syncwarp();

    /* ======= scores app[i] (pixel-packed), lane = column j ======= */
    ull app[32];
#pragma unroll
    for (int i = 0; i < D_; i++) {
        ull a0 = 0ULL, a1 = 0ULL;
#pragma unroll
        for (int g = 0; g < 16; g++) {
            const ulonglong2 kk = *(const ulonglong2*)&sc[i*SC_ROWF + 4*g];
            a0 = f2fma(kk.x, q2[2*g],   a0);
            a1 = f2fma(kk.y, q2[2*g+1], a1);
        }
        app[i] = f2add(a0, a1);
    }

    /* ======= softmax over i, per pixel ======= */
    {
        const ull scl = f2dup(0.17677669529663687f);   /* 1/sqrt(32) */
        float mA = -1e30f, mB = -1e30f;
#pragma unroll
        for (int i = 0; i < D_; i++) {
            app[i] = f2mul(app[i], scl);
            const float2 p = f2unpack(app[i]);
            mA = fmaxf(mA, p.x); mB = fmaxf(mB, p.y);
        }
        float sA = 0.f, sB = 0.f;
#pragma unroll
        for (int i = 0; i < D_; i++) {
            const float2 p = f2unpack(app[i]);
            const float eA = __expf(p.x - mA);
            const float eB = __expf(p.y - mB);
            app[i] = f2pack(eA, eB);
            sA += eA; sB += eB;
        }
        const ull inv = f2pack(1.0f/sA, 1.0f/sB);
#pragma unroll
        for (int i = 0; i < D_; i++) app[i] = f2mul(app[i], inv);
    }
    __syncwarp();   /* all lanes done reading kT -> safe to overwrite with vS */

    /* ================= V pass -> vS[s][i=lane] (overwrites kT) ============ */
    {
        ull vA[16], vB[16];
#pragma unroll
        for (int sp = 0; sp < 16; sp++) {
            const ull bb = *(const ull*)&cBV[2*sp];
            vA[sp] = bb; vB[sp] = bb;
        }
        PROJ_PASS(cWVT, vA, vB);
#pragma unroll
        for (int sp = 0; sp < 16; sp++) {
            const float2 a2 = f2unpack(vA[sp]);
            const float2 b2 = f2unpack(vB[sp]);
            *(ull*)&sc[(2*sp  )*SC_ROWF + 2*lane] = f2pack(a2.x, b2.x);
            *(ull*)&sc[(2*sp+1)*SC_ROWF + 2*lane] = f2pack(a2.y, b2.y);
        }
    }
    __syncwarp();

    /* ======= o[s] pixel-packed, then repack to s-pairs per pixel ======= */
    ull oA[16], oB[16];
    {
        ull opp[32];
#pragma unroll
        for (int s = 0; s < S_; s++) {
            ull a0 = 0ULL, a1 = 0ULL;
#pragma unroll
            for (int g = 0; g < 16; g++) {
                const ulonglong2 vv = *(const ulonglong2*)&sc[s*SC_ROWF + 4*g];
                a0 = f2fma(vv.x, app[2*g],   a0);
                a1 = f2fma(vv.y, app[2*g+1], a1);
            }
            opp[s] = f2add(a0, a1);
        }
#pragma unroll
        for (int sp = 0; sp < 16; sp++) {
            const float2 p0 = f2unpack(opp[2*sp]);
            const float2 p1 = f2unpack(opp[2*sp+1]);
            oA[sp] = f2pack(p0.x, p1.x);
            oB[sp] = f2pack(p0.y, p1.y);
        }
    }
    __syncthreads();   /* x-tile fully consumed -> reuse as otile */

    /* ======= outproj -> otile[c][2*lane + pix], overlays x-tile ======= */
    float* ot = sm + OFF_XT + warp*OTW;
#pragma unroll 4
    for (int c = 0; c < C_; c++) {
        ull aA0 = 0ULL, aA1 = 0ULL, aB0 = 0ULL, aB1 = 0ULL;
#pragma unroll
        for (int g = 0; g < 8; g++) {
            const ulonglong2 ww = *(const ulonglong2*)&cWO[c*S_ + 4*g];
            aA0 = f2fma(ww.x, oA[2*g],   aA0);
            aA1 = f2fma(ww.y, oA[2*g+1], aA1);
            aB0 = f2fma(ww.x, oB[2*g],   aB0);
            aB1 = f2fma(ww.y, oB[2*g+1], aB1);
        }
        const float2 pA = f2unpack(f2add(aA0, aA1));
        const float2 pB = f2unpack(f2add(aB0, aB1));
        const float bo = cBO[c];
        *(ull*)&ot[c*OT_ROWF + 2*lane] = f2pack(pA.x + pA.y + bo, pB.x + pB.y + bo);
    }
    __syncthreads();

    /* ======= final: out = otile + residual (x re-read from global) ======= */
    for (int e = tid; e < C_*D_; e += 64) {
        const int d = e & 31;
        const int c = e >> 5;
        const float4 xr = *(const float4*)&x[xbase + c*DHW_ + d*HW_];
        float4 r;
        r.x = xr.x + sm[OFF_XT + 0*OTW + c*OT_ROWF + 2*d + 0];
        r.y = xr.y + sm[OFF_XT + 0*OTW + c*OT_ROWF + 2*d + 1];
        r.z = xr.z + sm[OFF_XT + 1*OTW + c*OT_ROWF + 2*d + 0];
        r.w = xr.w + sm[OFF_XT + 1*OTW + c*OT_ROWF + 2*d + 1];
        *(float4*)&out[xbase + c*DHW_ + d*HW_] = r;
    }
}

extern "C" void kernel_launch(void* const* d_in, const int* in_sizes, int n_in,
                              void* d_out, int out_size)
{
    const float* x  = (const float*)d_in[0];
    float* out = (float*)d_out;

    /* 1) transpose k/q/v weights into staging buffer */
    transpose_weights<<<2, 1024>>>((const float*)d_in[1],
                                   (const float*)d_in[3],
                                   (const float*)d_in[5]);

    /* 2) staging -> constant symbols (D2D), plus direct copies */
    void* gwt = nullptr;
    cudaGetSymbolAddress(&gwt, g_wt);
    const float* g = (const float*)gwt;
    cudaMemcpyToSymbolAsync(cWKT, g,             C_*S_*sizeof(float), 0, cudaMemcpyDeviceToDevice, 0);
    cudaMemcpyToSymbolAsync(cWQT, g +   C_*S_,   C_*S_*sizeof(float), 0, cudaMemcpyDeviceToDevice, 0);
    cudaMemcpyToSymbolAsync(cWVT, g + 2*C_*S_,   C_*S_*sizeof(float), 0, cudaMemcpyDeviceToDevice, 0);
    cudaMemcpyToSymbolAsync(cBK, d_in[2], S_*sizeof(float),    0, cudaMemcpyDeviceToDevice, 0);
    cudaMemcpyToSymbolAsync(cBQ, d_in[4], S_*sizeof(float),    0, cudaMemcpyDeviceToDevice, 0);
    cudaMemcpyToSymbolAsync(cBV, d_in[6], S_*sizeof(float),    0, cudaMemcpyDeviceToDevice, 0);
    cudaMemcpyToSymbolAsync(cWO, d_in[7], C_*S_*sizeof(float), 0, cudaMemcpyDeviceToDevice, 0);
    cudaMemcpyToSymbolAsync(cBO, d_in[8], C_*sizeof(float),    0, cudaMemcpyDeviceToDevice, 0);

    /* 3) main kernel */
    const size_t smem_bytes = (size_t)SMEM_FLOATS * sizeof(float);
    cudaFuncSetAttribute(attn_fused_kernel,
                         cudaFuncAttributeMaxDynamicSharedMemorySize,
                         (int)smem_bytes);
    const int grid = 4 * 64 * 16;   /* B * H * (W/4) = 4096 */
    attn_fused_kernel<<<grid, 64, smem_bytes>>>(x, out);
}